// round 12
// baseline (speedup 1.0000x reference)
#include <cuda_runtime.h>
#include <cstdint>

#define B 8
#define O 2048
#define Q 2048
#define D 128
#define KT 10      // expansion terms k = 0..9 (remainder <= 7.5e-7 rel at x<=1)
#define GS 12      // g_s row stride (floats), 16B-aligned
#define NCH 64     // obs chunks per batch
#define CH 32      // obs rows per chunk

// Scratch (allocation-free rule: device globals; zero-initialized at load).
// g_M / g_msum_in are atomic accumulators; kernel B consumes AND re-zeros
// them each call, so every kernel_launch invocation starts from zeros.
__device__ float g_M[B * KT * D];        // accumulated moments
__device__ float g_msum_in[B * KT];      // accumulated weight sums
__device__ __align__(16) float g_Mp[B * KT * D];   // projected moments
__device__ __align__(16) float g_msum[B * KT];     // weight-sum moments (for C)

__constant__ float c_invk[KT] = {0.f, 1.f, 1.f/2, 1.f/3, 1.f/4, 1.f/5, 1.f/6,
                                 1.f/7, 1.f/8, 1.f/9};

// PDL: wait for the upstream grid's memory to be visible (sm_90+ PTX).
__device__ __forceinline__ void grid_dep_wait() {
    asm volatile("griddepcontrol.wait;" ::: "memory");
}

// ---------------------------------------------------------------------------
// Kernel A: per (batch, 32-obs chunk) moments, reduced across CTAs via RED.
//   g_k(o) = mask_o * exp(-0.5*c2*t_o^2) * (c2*t_o)^k / k!
//   g_M[b][k][e] += sum_o g_k(o)*emb[o][e] ;  g_msum_in[b][k] += sum_o g_k(o)
// 512 CTAs x 256 threads. Thread owns an e-PAIR (float2) and 8 rows:
//   e2 = 2*(tid&63), quarter qa = tid>>6. Loads in-loop (ptxas pipelines).
// ---------------------------------------------------------------------------
__global__ __launch_bounds__(256) void k_moments(
    const float* __restrict__ obs_emb,
    const float* __restrict__ obs_times,
    const float* __restrict__ obs_mask,
    const float* __restrict__ log_sigma)
{
    __shared__ __align__(16) float g_s[CH * GS];        // 10 used, pad to 12
    __shared__ __align__(16) float red[3 * KT * D];     // quarters 1..3 (15KB)

    const int tid = threadIdx.x;
    const int c   = blockIdx.x;
    const int b   = blockIdx.y;
    const int o0  = c * CH;
    const float c2 = __expf(-2.0f * log_sigma[0]);   // 1/sigma^2

    // Phase 1: 32 threads compute g_k rows
    if (tid < CH) {
        const int o = o0 + tid;
        const float t  = obs_times[b * O + o];
        const float mk = obs_mask[b * O + o];
        const float xx = c2 * t;
        float g = mk * __expf(-0.5f * c2 * t * t);
        g_s[tid * GS + 0] = g;
#pragma unroll
        for (int k = 1; k < KT; ++k) {
            g *= xx * c_invk[k];
            g_s[tid * GS + k] = g;
        }
    }
    __syncthreads();

    // ms partials -> atomic accumulate
    if (tid < KT) {
        float s = 0.0f;
#pragma unroll
        for (int o = 0; o < CH; ++o) s += g_s[o * GS + tid];
        atomicAdd(&g_msum_in[b * KT + tid], s);
    }

    // Phase 2: 8 rows per thread, float2 e-pair, loads in-loop.
    const int e2 = (tid & 63) * 2;
    const int qa = tid >> 6;            // 0..3, 8 rows each
    float2 acc[KT];
#pragma unroll
    for (int k = 0; k < KT; ++k) acc[k] = make_float2(0.f, 0.f);

    const float* ebase = obs_emb + ((size_t)(b * O) + o0 + qa * 8) * D + e2;
    const float* gbase = g_s + qa * 8 * GS;
#pragma unroll
    for (int oo = 0; oo < 8; ++oo) {
        const float2 xv = *(const float2*)(ebase + (size_t)oo * D);
        const float4 ga = *(const float4*)(gbase + oo * GS + 0);
        const float4 gb = *(const float4*)(gbase + oo * GS + 4);
        const float2 gc = *(const float2*)(gbase + oo * GS + 8);
        acc[0].x = fmaf(ga.x, xv.x, acc[0].x); acc[0].y = fmaf(ga.x, xv.y, acc[0].y);
        acc[1].x = fmaf(ga.y, xv.x, acc[1].x); acc[1].y = fmaf(ga.y, xv.y, acc[1].y);
        acc[2].x = fmaf(ga.z, xv.x, acc[2].x); acc[2].y = fmaf(ga.z, xv.y, acc[2].y);
        acc[3].x = fmaf(ga.w, xv.x, acc[3].x); acc[3].y = fmaf(ga.w, xv.y, acc[3].y);
        acc[4].x = fmaf(gb.x, xv.x, acc[4].x); acc[4].y = fmaf(gb.x, xv.y, acc[4].y);
        acc[5].x = fmaf(gb.y, xv.x, acc[5].x); acc[5].y = fmaf(gb.y, xv.y, acc[5].y);
        acc[6].x = fmaf(gb.z, xv.x, acc[6].x); acc[6].y = fmaf(gb.z, xv.y, acc[6].y);
        acc[7].x = fmaf(gb.w, xv.x, acc[7].x); acc[7].y = fmaf(gb.w, xv.y, acc[7].y);
        acc[8].x = fmaf(gc.x, xv.x, acc[8].x); acc[8].y = fmaf(gc.x, xv.y, acc[8].y);
        acc[9].x = fmaf(gc.y, xv.x, acc[9].x); acc[9].y = fmaf(gc.y, xv.y, acc[9].y);
    }

    // combine the four quarters via SMEM (1..3 store, 0 sums + RED.ADD)
    if (qa > 0) {
        float* dst = red + (qa - 1) * KT * D + e2;
#pragma unroll
        for (int k = 0; k < KT; ++k) *(float2*)(dst + k * D) = acc[k];
    }
    __syncthreads();
    if (qa == 0) {
        float* dst = g_M + (size_t)(b * KT) * D + e2;
        const float* r0 = red + e2;
#pragma unroll
        for (int k = 0; k < KT; ++k) {
            const float2 v1 = *(const float2*)(r0 + k * D);
            const float2 v2 = *(const float2*)(r0 + KT * D + k * D);
            const float2 v3 = *(const float2*)(r0 + 2 * KT * D + k * D);
            atomicAdd(dst + k * D,     acc[k].x + v1.x + v2.x + v3.x);
            atomicAdd(dst + k * D + 1, acc[k].y + v1.y + v2.y + v3.y);
        }
    }
}

// ---------------------------------------------------------------------------
// Kernel B: project accumulated moments through W; consume-and-rezero the
// atomic buffers so the next kernel_launch call starts from zeros.
//   Mp[b][k][e'] = sum_e W[e'][e] * g_M[b][k][e]
// One CTA per (b, k), 128 threads. PDL: waits on A's completion.
// ---------------------------------------------------------------------------
__global__ __launch_bounds__(128) void k_project(
    const float* __restrict__ W_proj)
{
    __shared__ __align__(16) float m_s[D];
    const int e = threadIdx.x;
    const int k = blockIdx.x % KT;
    const int b = blockIdx.x / KT;

    grid_dep_wait();   // A's g_M / g_msum_in now visible

    float* mcell = g_M + (size_t)(b * KT + k) * D + e;
    m_s[e] = *mcell;
    *mcell = 0.0f;                       // restore zero state
    if (e == 0) {
        g_msum[b * KT + k] = g_msum_in[b * KT + k];
        g_msum_in[b * KT + k] = 0.0f;    // restore zero state
    }
    __syncthreads();

    // thread e = output dim: dot(W[e][:], m)
    const float4* wrow = (const float4*)(W_proj + (size_t)e * D);
    float dot = 0.0f;
#pragma unroll
    for (int i = 0; i < D / 4; ++i) {
        float4 w4 = wrow[i];
        const float4 m4 = *(const float4*)&m_s[i * 4];
        dot += w4.x * m4.x + w4.y * m4.y + w4.z * m4.z + w4.w * m4.w;
    }
    g_Mp[(size_t)(b * KT + k) * D + e] = dot;
}

// ---------------------------------------------------------------------------
// Kernel C: combine. out[q][e'] = (sum_k f_k(q) Mp[k][e']) / (sum_k f_k msum[k]) + b[e']
// Thread owns 4 e-cols and FOUR q's with interleaved f-chains (amortizes the
// mp register load over 64B of output). PDL preamble before wait.
// 512 CTAs (32 q each), 256 threads.
// ---------------------------------------------------------------------------
__global__ __launch_bounds__(256) void k_combine(
    const float* __restrict__ query_times,
    const float* __restrict__ log_sigma,
    const float* __restrict__ b_proj,
    float* __restrict__ out)
{
    const int tid = threadIdx.x;
    const int b   = blockIdx.y;
    const int q0  = blockIdx.x * 32;
    const int e   = (tid & 31) * 4;
    const int qh  = tid >> 5;          // 0..7, 4 q's each

    // ---- preamble (independent of B's output) ----
    const float* qtp = query_times + b * Q + q0 + qh * 4;
    float qt[4], f[4];
#pragma unroll
    for (int j = 0; j < 4; ++j) qt[j] = qtp[j];
    const float c2 = __expf(-2.0f * log_sigma[0]);
    const float4 bp = *(const float4*)&b_proj[e];
#pragma unroll
    for (int j = 0; j < 4; ++j) f[j] = __expf(-0.5f * c2 * qt[j] * qt[j]);

    grid_dep_wait();   // B's g_Mp / g_msum now visible

    float4 mp[KT];
    float  ms[KT];
    const float* mpb = g_Mp + (size_t)b * KT * D + e;
    const float* msb = g_msum + b * KT;
#pragma unroll
    for (int k = 0; k < KT; ++k) {
        mp[k] = *(const float4*)(mpb + k * D);
        ms[k] = msb[k];
    }

    float4 n[4];
    float  d[4];
#pragma unroll
    for (int j = 0; j < 4; ++j) {
        n[j].x = f[j] * mp[0].x; n[j].y = f[j] * mp[0].y;
        n[j].z = f[j] * mp[0].z; n[j].w = f[j] * mp[0].w;
        d[j] = f[j] * ms[0];
    }
#pragma unroll
    for (int k = 1; k < KT; ++k) {
#pragma unroll
        for (int j = 0; j < 4; ++j) {
            f[j] *= qt[j];
            n[j].x = fmaf(f[j], mp[k].x, n[j].x);
            n[j].y = fmaf(f[j], mp[k].y, n[j].y);
            n[j].z = fmaf(f[j], mp[k].z, n[j].z);
            n[j].w = fmaf(f[j], mp[k].w, n[j].w);
            d[j] = fmaf(f[j], ms[k], d[j]);
        }
    }
    float* ob = out + ((size_t)(b * Q) + q0 + qh * 4) * D + e;
#pragma unroll
    for (int j = 0; j < 4; ++j) {
        const float inv = __fdividef(1.0f, fmaxf(d[j], 1e-8f));
        float4 v;
        v.x = fmaf(n[j].x, inv, bp.x);
        v.y = fmaf(n[j].y, inv, bp.y);
        v.z = fmaf(n[j].z, inv, bp.z);
        v.w = fmaf(n[j].w, inv, bp.w);
        *(float4*)(ob + (size_t)j * D) = v;
    }
}

// ---------------------------------------------------------------------------
extern "C" void kernel_launch(void* const* d_in, const int* in_sizes, int n_in,
                              void* d_out, int out_size) {
    const float* obs_emb     = (const float*)d_in[0];
    const float* obs_times   = (const float*)d_in[1];
    const float* query_times = (const float*)d_in[2];
    const float* obs_mask    = (const float*)d_in[3];
    const float* log_sigma   = (const float*)d_in[4];
    const float* W_proj      = (const float*)d_in[5];
    const float* b_proj      = (const float*)d_in[6];
    float* out = (float*)d_out;

    // A: normal launch
    dim3 gA(NCH, B);
    k_moments<<<gA, 256>>>(obs_emb, obs_times, obs_mask, log_sigma);

    // B, C: programmatic dependent launches (overlap ramp with predecessor drain)
    cudaLaunchAttribute attr[1];
    attr[0].id = cudaLaunchAttributeProgrammaticStreamSerialization;
    attr[0].val.programmaticStreamSerializationAllowed = 1;

    {
        cudaLaunchConfig_t cfg = {};
        cfg.gridDim  = dim3(B * KT);
        cfg.blockDim = dim3(128);
        cfg.stream   = 0;
        cfg.attrs    = attr;
        cfg.numAttrs = 1;
        cudaLaunchKernelEx(&cfg, k_project, W_proj);
    }
    {
        cudaLaunchConfig_t cfg = {};
        cfg.gridDim  = dim3(Q / 32, B);
        cfg.blockDim = dim3(256);
        cfg.stream   = 0;
        cfg.attrs    = attr;
        cfg.numAttrs = 1;
        cudaLaunchKernelEx(&cfg, k_combine, query_times, log_sigma, b_proj, out);
    }
}

// round 13
// speedup vs baseline: 1.0253x; 1.0253x over previous
#include <cuda_runtime.h>
#include <cstdint>

#define B 8
#define O 2048
#define Q 2048
#define D 128
#define KT 10      // expansion terms k = 0..9 (remainder <= 7.5e-7 rel at x<=1)
#define GS 12      // g_s row stride (floats), 16B-aligned
#define NCH 64     // obs chunks per batch
#define CH 32      // obs rows per chunk

// Scratch (allocation-free rule: device globals; zero-initialized at load).
// g_M / g_msum_in are atomic accumulators; kernel B consumes AND re-zeros
// them each call, so every kernel_launch invocation starts from zeros.
__device__ float g_M[B * KT * D];        // accumulated moments
__device__ float g_msum_in[B * KT];      // accumulated weight sums
__device__ __align__(16) float g_Mp[B * KT * D];   // projected moments
__device__ __align__(16) float g_msum[B * KT];     // weight-sum moments (for C)

__constant__ float c_invk[KT] = {0.f, 1.f, 1.f/2, 1.f/3, 1.f/4, 1.f/5, 1.f/6,
                                 1.f/7, 1.f/8, 1.f/9};

// PDL: wait for the upstream grid's memory to be visible (sm_90+ PTX).
__device__ __forceinline__ void grid_dep_wait() {
    asm volatile("griddepcontrol.wait;" ::: "memory");
}

// ---------------------------------------------------------------------------
// Kernel A (exact R11 shape — best measured: 7.26us):
// per (batch, 32-obs chunk) moments, reduced across CTAs via RED.
//   g_k(o) = mask_o * exp(-0.5*c2*t_o^2) * (c2*t_o)^k / k!
//   g_M[b][k][e] += sum_o g_k(o)*emb[o][e] ;  g_msum_in[b][k] += sum_o g_k(o)
// 512 CTAs x 256 threads, e = tid&127, half = tid>>7 owns 16 rows,
// x loads in-loop (ptxas software-pipelines them).
// ---------------------------------------------------------------------------
__global__ __launch_bounds__(256) void k_moments(
    const float* __restrict__ obs_emb,
    const float* __restrict__ obs_times,
    const float* __restrict__ obs_mask,
    const float* __restrict__ log_sigma)
{
    __shared__ __align__(16) float g_s[CH * GS];   // 10 used, pad to 12
    __shared__ __align__(16) float red[KT * D];

    const int tid = threadIdx.x;
    const int c   = blockIdx.x;
    const int b   = blockIdx.y;
    const int o0  = c * CH;
    const float c2 = __expf(-2.0f * log_sigma[0]);   // 1/sigma^2

    // Phase 1: 32 threads compute g_k rows
    if (tid < CH) {
        const int o = o0 + tid;
        const float t  = obs_times[b * O + o];
        const float mk = obs_mask[b * O + o];
        const float xx = c2 * t;
        float g = mk * __expf(-0.5f * c2 * t * t);
        g_s[tid * GS + 0] = g;
#pragma unroll
        for (int k = 1; k < KT; ++k) {
            g *= xx * c_invk[k];
            g_s[tid * GS + k] = g;
        }
    }
    __syncthreads();

    // ms partials -> atomic accumulate
    if (tid < KT) {
        float s = 0.0f;
#pragma unroll
        for (int o = 0; o < CH; ++o) s += g_s[o * GS + tid];
        atomicAdd(&g_msum_in[b * KT + tid], s);
    }

    // Phase 2: accumulate moments over 16 rows per thread, loads in-loop.
    const int e    = tid & 127;
    const int half = tid >> 7;
    float acc[KT];
#pragma unroll
    for (int k = 0; k < KT; ++k) acc[k] = 0.0f;

    const float* ebase = obs_emb + ((size_t)(b * O) + o0 + half * 16) * D + e;
    const float* gbase = g_s + half * 16 * GS;
#pragma unroll
    for (int oo = 0; oo < 16; ++oo) {
        const float xv = ebase[(size_t)oo * D];
        const float4 ga = *(const float4*)(gbase + oo * GS + 0);
        const float4 gb = *(const float4*)(gbase + oo * GS + 4);
        const float2 gc = *(const float2*)(gbase + oo * GS + 8);
        acc[0] = fmaf(ga.x, xv, acc[0]);   acc[1] = fmaf(ga.y, xv, acc[1]);
        acc[2] = fmaf(ga.z, xv, acc[2]);   acc[3] = fmaf(ga.w, xv, acc[3]);
        acc[4] = fmaf(gb.x, xv, acc[4]);   acc[5] = fmaf(gb.y, xv, acc[5]);
        acc[6] = fmaf(gb.z, xv, acc[6]);   acc[7] = fmaf(gb.w, xv, acc[7]);
        acc[8] = fmaf(gc.x, xv, acc[8]);   acc[9] = fmaf(gc.y, xv, acc[9]);
    }

    // combine the two halves via SMEM, then RED.ADD into g_M
    if (half == 1) {
#pragma unroll
        for (int k = 0; k < KT; ++k) red[k * D + e] = acc[k];
    }
    __syncthreads();
    if (half == 0) {
        float* dst = g_M + (size_t)(b * KT) * D + e;
        const float* r0 = red + e;
#pragma unroll
        for (int k = 0; k < KT; ++k)
            atomicAdd(dst + k * D, acc[k] + r0[k * D]);
    }
}

// ---------------------------------------------------------------------------
// Kernel B: project accumulated moments through W; consume-and-rezero the
// atomic buffers so the next kernel_launch call starts from zeros.
//   Mp[b][k][e'] = sum_e W[e'][e] * g_M[b][k][e]
// One CTA per (b, k), 128 threads. PDL: waits on A's completion.
// ---------------------------------------------------------------------------
__global__ __launch_bounds__(128) void k_project(
    const float* __restrict__ W_proj)
{
    __shared__ __align__(16) float m_s[D];
    const int e = threadIdx.x;
    const int k = blockIdx.x % KT;
    const int b = blockIdx.x / KT;

    grid_dep_wait();   // A's g_M / g_msum_in now visible

    float* mcell = g_M + (size_t)(b * KT + k) * D + e;
    m_s[e] = *mcell;
    *mcell = 0.0f;                       // restore zero state
    if (e == 0) {
        g_msum[b * KT + k] = g_msum_in[b * KT + k];
        g_msum_in[b * KT + k] = 0.0f;    // restore zero state
    }
    __syncthreads();

    // thread e = output dim: dot(W[e][:], m)
    const float4* wrow = (const float4*)(W_proj + (size_t)e * D);
    float dot = 0.0f;
#pragma unroll
    for (int i = 0; i < D / 4; ++i) {
        float4 w4 = wrow[i];
        const float4 m4 = *(const float4*)&m_s[i * 4];
        dot += w4.x * m4.x + w4.y * m4.y + w4.z * m4.z + w4.w * m4.w;
    }
    g_Mp[(size_t)(b * KT + k) * D + e] = dot;
}

// ---------------------------------------------------------------------------
// Kernel C (R12 4-q shape — measured -0.76us vs 2-q):
// out[q][e'] = (sum_k f_k(q) Mp[k][e']) / (sum_k f_k msum[k]) + b[e']
// Thread owns 4 e-cols and FOUR q's with interleaved f-chains. PDL preamble
// before the wait. 512 CTAs (32 q each), 256 threads.
// ---------------------------------------------------------------------------
__global__ __launch_bounds__(256) void k_combine(
    const float* __restrict__ query_times,
    const float* __restrict__ log_sigma,
    const float* __restrict__ b_proj,
    float* __restrict__ out)
{
    const int tid = threadIdx.x;
    const int b   = blockIdx.y;
    const int q0  = blockIdx.x * 32;
    const int e   = (tid & 31) * 4;
    const int qh  = tid >> 5;          // 0..7, 4 q's each

    // ---- preamble (independent of B's output) ----
    const float* qtp = query_times + b * Q + q0 + qh * 4;
    float qt[4], f[4];
#pragma unroll
    for (int j = 0; j < 4; ++j) qt[j] = qtp[j];
    const float c2 = __expf(-2.0f * log_sigma[0]);
    const float4 bp = *(const float4*)&b_proj[e];
#pragma unroll
    for (int j = 0; j < 4; ++j) f[j] = __expf(-0.5f * c2 * qt[j] * qt[j]);

    grid_dep_wait();   // B's g_Mp / g_msum now visible

    float4 mp[KT];
    float  ms[KT];
    const float* mpb = g_Mp + (size_t)b * KT * D + e;
    const float* msb = g_msum + b * KT;
#pragma unroll
    for (int k = 0; k < KT; ++k) {
        mp[k] = *(const float4*)(mpb + k * D);
        ms[k] = msb[k];
    }

    float4 n[4];
    float  d[4];
#pragma unroll
    for (int j = 0; j < 4; ++j) {
        n[j].x = f[j] * mp[0].x; n[j].y = f[j] * mp[0].y;
        n[j].z = f[j] * mp[0].z; n[j].w = f[j] * mp[0].w;
        d[j] = f[j] * ms[0];
    }
#pragma unroll
    for (int k = 1; k < KT; ++k) {
#pragma unroll
        for (int j = 0; j < 4; ++j) {
            f[j] *= qt[j];
            n[j].x = fmaf(f[j], mp[k].x, n[j].x);
            n[j].y = fmaf(f[j], mp[k].y, n[j].y);
            n[j].z = fmaf(f[j], mp[k].z, n[j].z);
            n[j].w = fmaf(f[j], mp[k].w, n[j].w);
            d[j] = fmaf(f[j], ms[k], d[j]);
        }
    }
    float* ob = out + ((size_t)(b * Q) + q0 + qh * 4) * D + e;
#pragma unroll
    for (int j = 0; j < 4; ++j) {
        const float inv = __fdividef(1.0f, fmaxf(d[j], 1e-8f));
        float4 v;
        v.x = fmaf(n[j].x, inv, bp.x);
        v.y = fmaf(n[j].y, inv, bp.y);
        v.z = fmaf(n[j].z, inv, bp.z);
        v.w = fmaf(n[j].w, inv, bp.w);
        *(float4*)(ob + (size_t)j * D) = v;
    }
}

// ---------------------------------------------------------------------------
extern "C" void kernel_launch(void* const* d_in, const int* in_sizes, int n_in,
                              void* d_out, int out_size) {
    const float* obs_emb     = (const float*)d_in[0];
    const float* obs_times   = (const float*)d_in[1];
    const float* query_times = (const float*)d_in[2];
    const float* obs_mask    = (const float*)d_in[3];
    const float* log_sigma   = (const float*)d_in[4];
    const float* W_proj      = (const float*)d_in[5];
    const float* b_proj      = (const float*)d_in[6];
    float* out = (float*)d_out;

    // A: normal launch
    dim3 gA(NCH, B);
    k_moments<<<gA, 256>>>(obs_emb, obs_times, obs_mask, log_sigma);

    // B, C: programmatic dependent launches (overlap ramp with predecessor drain)
    cudaLaunchAttribute attr[1];
    attr[0].id = cudaLaunchAttributeProgrammaticStreamSerialization;
    attr[0].val.programmaticStreamSerializationAllowed = 1;

    {
        cudaLaunchConfig_t cfg = {};
        cfg.gridDim  = dim3(B * KT);
        cfg.blockDim = dim3(128);
        cfg.stream   = 0;
        cfg.attrs    = attr;
        cfg.numAttrs = 1;
        cudaLaunchKernelEx(&cfg, k_project, W_proj);
    }
    {
        cudaLaunchConfig_t cfg = {};
        cfg.gridDim  = dim3(Q / 32, B);
        cfg.blockDim = dim3(256);
        cfg.stream   = 0;
        cfg.attrs    = attr;
        cfg.numAttrs = 1;
        cudaLaunchKernelEx(&cfg, k_combine, query_times, log_sigma, b_proj, out);
    }
}

// round 14
// speedup vs baseline: 1.0273x; 1.0020x over previous
#include <cuda_runtime.h>
#include <cstdint>

#define B 8
#define O 2048
#define Q 2048
#define D 128
#define KT 10      // expansion terms k = 0..9 (remainder <= 7.5e-7 rel at x<=1)
#define GS 12      // g_s row stride (floats), 16B-aligned
#define NCH 64     // obs chunks per batch
#define CH 32      // obs rows per chunk

// Scratch (allocation-free rule: device globals; zero-initialized at load).
// g_M / g_msum_in are atomic accumulators; kernel B consumes AND re-zeros
// them each call, so every kernel_launch invocation starts from zeros.
__device__ float g_M[B * KT * D];        // accumulated moments
__device__ float g_msum_in[B * KT];      // accumulated weight sums
__device__ __align__(16) float g_Mp[B * KT * D];   // projected moments
__device__ __align__(16) float g_msum[B * KT];     // weight-sum moments (for C)

__constant__ float c_invk[KT] = {0.f, 1.f, 1.f/2, 1.f/3, 1.f/4, 1.f/5, 1.f/6,
                                 1.f/7, 1.f/8, 1.f/9};

// PDL: wait for the upstream grid's memory to be visible (sm_90+ PTX).
__device__ __forceinline__ void grid_dep_wait() {
    asm volatile("griddepcontrol.wait;" ::: "memory");
}

__device__ __forceinline__ uint32_t smem_u32(const void* p) {
    uint32_t a;
    asm("{ .reg .u64 t; cvta.to.shared.u64 t, %1; cvt.u32.u64 %0, t; }"
        : "=r"(a) : "l"(p));
    return a;
}

// ---------------------------------------------------------------------------
// Kernel A: per (batch, 32-obs chunk) moments, reduced across CTAs via RED.
//   g_k(o) = mask_o * exp(-0.5*c2*t_o^2) * (c2*t_o)^k / k!
//   g_M[b][k][e] += sum_o g_k(o)*emb[o][e] ;  g_msum_in[b][k] += sum_o g_k(o)
// 512 CTAs x 256 threads. The 16KB emb tile is streamed into SMEM via
// cp.async (1024 x 16B in flight, zero register cost) BEFORE the g phase;
// phase 2 is then pure LDS+FMA with no long-scoreboard stalls.
// ---------------------------------------------------------------------------
__global__ __launch_bounds__(256) void k_moments(
    const float* __restrict__ obs_emb,
    const float* __restrict__ obs_times,
    const float* __restrict__ obs_mask,
    const float* __restrict__ log_sigma)
{
    __shared__ __align__(16) float g_s[CH * GS];   // 10 used, pad to 12
    __shared__ __align__(16) float red[KT * D];
    __shared__ __align__(16) float tile[CH * D];   // 16KB emb tile

    const int tid = threadIdx.x;
    const int c   = blockIdx.x;
    const int b   = blockIdx.y;
    const int o0  = c * CH;

    // ---- Phase 0: stream the emb tile into SMEM (cp.async, 4x16B/thread) ----
    {
        const uint32_t tbase = smem_u32(tile);
        const float* src = obs_emb + ((size_t)(b * O) + o0) * D;
#pragma unroll
        for (int i = 0; i < 4; ++i) {
            const int idx = tid + i * 256;   // 16B chunk index (0..1023)
            asm volatile("cp.async.cg.shared.global [%0], [%1], 16;"
                :: "r"(tbase + idx * 16), "l"(src + idx * 4) : "memory");
        }
        asm volatile("cp.async.commit_group;" ::: "memory");
    }

    const float c2 = __expf(-2.0f * log_sigma[0]);   // 1/sigma^2

    // ---- Phase 1: 32 threads compute g_k rows (overlaps the async copy) ----
    if (tid < CH) {
        const int o = o0 + tid;
        const float t  = obs_times[b * O + o];
        const float mk = obs_mask[b * O + o];
        const float xx = c2 * t;
        float g = mk * __expf(-0.5f * c2 * t * t);
        g_s[tid * GS + 0] = g;
#pragma unroll
        for (int k = 1; k < KT; ++k) {
            g *= xx * c_invk[k];
            g_s[tid * GS + k] = g;
        }
    }
    asm volatile("cp.async.wait_group 0;" ::: "memory");
    __syncthreads();   // tile + g_s visible to all

    // ms partials -> atomic accumulate
    if (tid < KT) {
        float s = 0.0f;
#pragma unroll
        for (int o = 0; o < CH; ++o) s += g_s[o * GS + tid];
        atomicAdd(&g_msum_in[b * KT + tid], s);
    }

    // ---- Phase 2: accumulate moments over 16 rows per thread (SMEM only) ----
    const int e    = tid & 127;
    const int half = tid >> 7;
    float acc[KT];
#pragma unroll
    for (int k = 0; k < KT; ++k) acc[k] = 0.0f;

    const float* tbase = tile + half * 16 * D + e;
    const float* gbase = g_s + half * 16 * GS;
#pragma unroll
    for (int oo = 0; oo < 16; ++oo) {
        const float xv = tbase[oo * D];
        const float4 ga = *(const float4*)(gbase + oo * GS + 0);
        const float4 gb = *(const float4*)(gbase + oo * GS + 4);
        const float2 gc = *(const float2*)(gbase + oo * GS + 8);
        acc[0] = fmaf(ga.x, xv, acc[0]);   acc[1] = fmaf(ga.y, xv, acc[1]);
        acc[2] = fmaf(ga.z, xv, acc[2]);   acc[3] = fmaf(ga.w, xv, acc[3]);
        acc[4] = fmaf(gb.x, xv, acc[4]);   acc[5] = fmaf(gb.y, xv, acc[5]);
        acc[6] = fmaf(gb.z, xv, acc[6]);   acc[7] = fmaf(gb.w, xv, acc[7]);
        acc[8] = fmaf(gc.x, xv, acc[8]);   acc[9] = fmaf(gc.y, xv, acc[9]);
    }

    // combine the two halves via SMEM, then RED.ADD into g_M
    if (half == 1) {
#pragma unroll
        for (int k = 0; k < KT; ++k) red[k * D + e] = acc[k];
    }
    __syncthreads();
    if (half == 0) {
        float* dst = g_M + (size_t)(b * KT) * D + e;
        const float* r0 = red + e;
#pragma unroll
        for (int k = 0; k < KT; ++k)
            atomicAdd(dst + k * D, acc[k] + r0[k * D]);
    }
}

// ---------------------------------------------------------------------------
// Kernel B: project accumulated moments through W; consume-and-rezero the
// atomic buffers so the next kernel_launch call starts from zeros.
//   Mp[b][k][e'] = sum_e W[e'][e] * g_M[b][k][e]
// One CTA per (b, k), 128 threads. PDL: waits on A's completion.
// ---------------------------------------------------------------------------
__global__ __launch_bounds__(128) void k_project(
    const float* __restrict__ W_proj)
{
    __shared__ __align__(16) float m_s[D];
    const int e = threadIdx.x;
    const int k = blockIdx.x % KT;
    const int b = blockIdx.x / KT;

    grid_dep_wait();   // A's g_M / g_msum_in now visible

    float* mcell = g_M + (size_t)(b * KT + k) * D + e;
    m_s[e] = *mcell;
    *mcell = 0.0f;                       // restore zero state
    if (e == 0) {
        g_msum[b * KT + k] = g_msum_in[b * KT + k];
        g_msum_in[b * KT + k] = 0.0f;    // restore zero state
    }
    __syncthreads();

    // thread e = output dim: dot(W[e][:], m)
    const float4* wrow = (const float4*)(W_proj + (size_t)e * D);
    float dot = 0.0f;
#pragma unroll
    for (int i = 0; i < D / 4; ++i) {
        float4 w4 = wrow[i];
        const float4 m4 = *(const float4*)&m_s[i * 4];
        dot += w4.x * m4.x + w4.y * m4.y + w4.z * m4.z + w4.w * m4.w;
    }
    g_Mp[(size_t)(b * KT + k) * D + e] = dot;
}

// ---------------------------------------------------------------------------
// Kernel C: combine. out[q][e'] = (sum_k f_k(q) Mp[k][e']) / (sum_k f_k msum[k]) + b[e']
// Thread owns 4 e-cols and FOUR q's with interleaved f-chains. PDL preamble
// before the wait. 512 CTAs (32 q each), 256 threads.
// ---------------------------------------------------------------------------
__global__ __launch_bounds__(256) void k_combine(
    const float* __restrict__ query_times,
    const float* __restrict__ log_sigma,
    const float* __restrict__ b_proj,
    float* __restrict__ out)
{
    const int tid = threadIdx.x;
    const int b   = blockIdx.y;
    const int q0  = blockIdx.x * 32;
    const int e   = (tid & 31) * 4;
    const int qh  = tid >> 5;          // 0..7, 4 q's each

    // ---- preamble (independent of B's output) ----
    const float* qtp = query_times + b * Q + q0 + qh * 4;
    float qt[4], f[4];
#pragma unroll
    for (int j = 0; j < 4; ++j) qt[j] = qtp[j];
    const float c2 = __expf(-2.0f * log_sigma[0]);
    const float4 bp = *(const float4*)&b_proj[e];
#pragma unroll
    for (int j = 0; j < 4; ++j) f[j] = __expf(-0.5f * c2 * qt[j] * qt[j]);

    grid_dep_wait();   // B's g_Mp / g_msum now visible

    float4 mp[KT];
    float  ms[KT];
    const float* mpb = g_Mp + (size_t)b * KT * D + e;
    const float* msb = g_msum + b * KT;
#pragma unroll
    for (int k = 0; k < KT; ++k) {
        mp[k] = *(const float4*)(mpb + k * D);
        ms[k] = msb[k];
    }

    float4 n[4];
    float  d[4];
#pragma unroll
    for (int j = 0; j < 4; ++j) {
        n[j].x = f[j] * mp[0].x; n[j].y = f[j] * mp[0].y;
        n[j].z = f[j] * mp[0].z; n[j].w = f[j] * mp[0].w;
        d[j] = f[j] * ms[0];
    }
#pragma unroll
    for (int k = 1; k < KT; ++k) {
#pragma unroll
        for (int j = 0; j < 4; ++j) {
            f[j] *= qt[j];
            n[j].x = fmaf(f[j], mp[k].x, n[j].x);
            n[j].y = fmaf(f[j], mp[k].y, n[j].y);
            n[j].z = fmaf(f[j], mp[k].z, n[j].z);
            n[j].w = fmaf(f[j], mp[k].w, n[j].w);
            d[j] = fmaf(f[j], ms[k], d[j]);
        }
    }
    float* ob = out + ((size_t)(b * Q) + q0 + qh * 4) * D + e;
#pragma unroll
    for (int j = 0; j < 4; ++j) {
        const float inv = __fdividef(1.0f, fmaxf(d[j], 1e-8f));
        float4 v;
        v.x = fmaf(n[j].x, inv, bp.x);
        v.y = fmaf(n[j].y, inv, bp.y);
        v.z = fmaf(n[j].z, inv, bp.z);
        v.w = fmaf(n[j].w, inv, bp.w);
        *(float4*)(ob + (size_t)j * D) = v;
    }
}

// ---------------------------------------------------------------------------
extern "C" void kernel_launch(void* const* d_in, const int* in_sizes, int n_in,
                              void* d_out, int out_size) {
    const float* obs_emb     = (const float*)d_in[0];
    const float* obs_times   = (const float*)d_in[1];
    const float* query_times = (const float*)d_in[2];
    const float* obs_mask    = (const float*)d_in[3];
    const float* log_sigma   = (const float*)d_in[4];
    const float* W_proj      = (const float*)d_in[5];
    const float* b_proj      = (const float*)d_in[6];
    float* out = (float*)d_out;

    // A: normal launch
    dim3 gA(NCH, B);
    k_moments<<<gA, 256>>>(obs_emb, obs_times, obs_mask, log_sigma);

    // B, C: programmatic dependent launches (overlap ramp with predecessor drain)
    cudaLaunchAttribute attr[1];
    attr[0].id = cudaLaunchAttributeProgrammaticStreamSerialization;
    attr[0].val.programmaticStreamSerializationAllowed = 1;

    {
        cudaLaunchConfig_t cfg = {};
        cfg.gridDim  = dim3(B * KT);
        cfg.blockDim = dim3(128);
        cfg.stream   = 0;
        cfg.attrs    = attr;
        cfg.numAttrs = 1;
        cudaLaunchKernelEx(&cfg, k_project, W_proj);
    }
    {
        cudaLaunchConfig_t cfg = {};
        cfg.gridDim  = dim3(Q / 32, B);
        cfg.blockDim = dim3(256);
        cfg.stream   = 0;
        cfg.attrs    = attr;
        cfg.numAttrs = 1;
        cudaLaunchKernelEx(&cfg, k_combine, query_times, log_sigma, b_proj, out);
    }
}